// round 7
// baseline (speedup 1.0000x reference)
#include <cuda_runtime.h>
#include <cstdint>

#define N_ROWS 32768
#define K_ANCH 32
#define D_FEAT 128

// --- packed f32x2 helpers (sm_103a; PTX-only, ptxas won't auto-fuse) ---
__device__ __forceinline__ uint64_t fma2(uint64_t a, uint64_t b, uint64_t c) {
    uint64_t r;
    asm("fma.rn.f32x2 %0, %1, %2, %3;" : "=l"(r) : "l"(a), "l"(b), "l"(c));
    return r;
}
__device__ __forceinline__ uint64_t mul2(uint64_t a, uint64_t b) {
    uint64_t r;
    asm("mul.rn.f32x2 %0, %1, %2;" : "=l"(r) : "l"(a), "l"(b));
    return r;
}
__device__ __forceinline__ uint64_t pack2(float lo, float hi) {
    uint64_t r;
    asm("mov.b64 %0, {%1, %2};" : "=l"(r) : "f"(lo), "f"(hi));
    return r;
}
__device__ __forceinline__ void unpack2(float& lo, float& hi, uint64_t v) {
    asm("mov.b64 {%0, %1}, %2;" : "=f"(lo), "=f"(hi) : "l"(v));
}

// Fold two composites at lane-xor offset `off` (natural k order, LSB-first).
// After all 5 folds, lane l holds the full cross-lane sum for k == l.
__device__ __forceinline__ float warp_fold(float a, float b, int off, int lane) {
    float r = (lane & off) ? a : b;
    float s = __shfl_xor_sync(0xFFFFFFFFu, r, off);
    return ((lane & off) ? b : a) + s;
}

// Single fused kernel, both branches (blockIdx.y). Warp per row n, float4 lane.
//   os[n,d]  = (1/K) sum_k dm[n,k] * x[idx[n,k], d]
//   op[n,k]  = dm[n,k] * dot(x[idx[n,k],:], w) + b      (in-register fold)
__global__ __launch_bounds__(256) void fused_kernel(
    const float* __restrict__ x1, const int* __restrict__ idx1, const float* __restrict__ dm1,
    const float* __restrict__ x2, const int* __restrict__ idx2, const float* __restrict__ dm2,
    const float* __restrict__ w,  const float* __restrict__ b_out,
    float* __restrict__ op1, float* __restrict__ os1,
    float* __restrict__ op2, float* __restrict__ os2)
{
    const int br = blockIdx.y;
    const float* __restrict__ x   = br ? x2   : x1;
    const int*   __restrict__ idx = br ? idx2 : idx1;
    const float* __restrict__ dm  = br ? dm2  : dm1;
    float*       __restrict__ op  = br ? op2  : op1;
    float*       __restrict__ os  = br ? os2  : os1;

    const int warp = threadIdx.x >> 5;
    const int lane = threadIdx.x & 31;
    const int n    = blockIdx.x * 8 + warp;

    // Metadata for 2 k's per int4: (off_2p, dm_2p, off_2p+1, dm_2p+1).
    __shared__ int4 s_meta[8][16];

    // Lane l owns metadata for k == l.
    const int   a = idx[n * K_ANCH + lane];    // coalesced
    const float d = dm [n * K_ANCH + lane];    // coalesced
    {
        int2* dst = reinterpret_cast<int2*>(&s_meta[warp][0]) + lane;
        *dst = make_int2(a * (int)(D_FEAT * sizeof(float)), __float_as_int(d));
    }
    __syncwarp();

    // This lane's 4-wide slice of w, kept packed.
    const ulonglong2 wp = *reinterpret_cast<const ulonglong2*>(
        reinterpret_cast<const float*>(w) + lane * 4);
    const uint64_t w01 = wp.x, w23 = wp.y;

    const char* __restrict__ xb = reinterpret_cast<const char*>(x);
    const int lane_byte = lane * 16;

    uint64_t acc01 = 0, acc23 = 0;   // packed (0.0f, 0.0f)

    float stk[6];
    int sp = 0;

    #pragma unroll
    for (int p = 0; p < 16; p++) {
        const int4 m = s_meta[warp][p];          // broadcast LDS.128
        const float d0 = __int_as_float(m.y);
        const float d1 = __int_as_float(m.w);
        const ulonglong2 v0 = *reinterpret_cast<const ulonglong2*>(xb + m.x + lane_byte);
        const ulonglong2 v1 = *reinterpret_cast<const ulonglong2*>(xb + m.z + lane_byte);

        // k = 2p
        {
            const uint64_t dp = pack2(d0, d0);
            acc01 = fma2(dp, v0.x, acc01);
            acc23 = fma2(dp, v0.y, acc23);
            uint64_t u = mul2(v0.x, w01);
            u = fma2(v0.y, w23, u);
            float lo, hi; unpack2(lo, hi, u);
            stk[sp++] = d0 * (lo + hi);
        }
        // k = 2p+1
        {
            const uint64_t dp = pack2(d1, d1);
            acc01 = fma2(dp, v1.x, acc01);
            acc23 = fma2(dp, v1.y, acc23);
            uint64_t u = mul2(v1.x, w01);
            u = fma2(v1.y, w23, u);
            float lo, hi; unpack2(lo, hi, u);
            stk[sp++] = d1 * (lo + hi);
        }

        // Eager binary-counter folding, LSB-first.
        const int i1 = 2 * p + 2;   // items completed
        #pragma unroll
        for (int j = 0; j < 5; j++) {
            if ((i1 & ((2 << j) - 1)) == 0) {
                const int off = 1 << j;
                sp -= 2;
                stk[sp] = warp_fold(stk[sp], stk[sp + 1], off, lane);
                sp += 1;
            }
        }
    }

    // stk[0]: lane l holds op-value for k == l (pre-bias).
    const float opv = stk[0] + __ldg(&b_out[0]);

    const uint64_t inv2 = pack2(1.0f / (float)K_ANCH, 1.0f / (float)K_ANCH);
    ulonglong2 outv;
    outv.x = mul2(acc01, inv2);
    outv.y = mul2(acc23, inv2);
    reinterpret_cast<ulonglong2*>(os)[n * (D_FEAT / 4) + lane] = outv;  // coalesced 512B
    op[n * K_ANCH + lane] = opv;                                       // coalesced 128B
}

extern "C" void kernel_launch(void* const* d_in, const int* in_sizes, int n_in,
                              void* d_out, int out_size) {
    const float* x1   = (const float*)d_in[0];
    const int*   idx1 = (const int*)  d_in[1];
    const float* dm1  = (const float*)d_in[2];
    const float* x2   = (const float*)d_in[3];
    const int*   idx2 = (const int*)  d_in[4];
    const float* dm2  = (const float*)d_in[5];
    const float* w    = (const float*)d_in[6];
    const float* b    = (const float*)d_in[7];

    float* out = (float*)d_out;
    float* op1 = out;                                       // [N, K]
    float* os1 = op1 + (size_t)N_ROWS * K_ANCH;             // [N, D]
    float* op2 = os1 + (size_t)N_ROWS * D_FEAT;             // [N, K]
    float* os2 = op2 + (size_t)N_ROWS * K_ANCH;             // [N, D]

    dim3 gg(N_ROWS / 8, 2);
    fused_kernel<<<gg, 256>>>(x1, idx1, dm1, x2, idx2, dm2, w, b,
                              op1, os1, op2, os2);
}

// round 8
// speedup vs baseline: 1.0419x; 1.0419x over previous
#include <cuda_runtime.h>

#define N_ROWS 32768
#define K_ANCH 32
#define D_FEAT 128

// Fold two composites at lane-xor offset `off` (natural k order, LSB-first).
// After all 5 folds, lane l holds the full cross-lane sum for k == l.
__device__ __forceinline__ float warp_fold(float a, float b, int off, int lane) {
    float r = (lane & off) ? a : b;
    float s = __shfl_xor_sync(0xFFFFFFFFu, r, off);
    return ((lane & off) ? b : a) + s;
}

// Single fused kernel, both branches (blockIdx.y). Warp per row n, float4 lane.
//   os[n,d]  = (1/K) sum_k dm[n,k] * x[idx[n,k], d]
//   op[n,k]  = dm[n,k] * dot(x[idx[n,k],:], w) + b      (in-register fold)
// Per-k math: acc = fma(d,v,acc) [4 FFMA]; o = d*dot(v,w) [1 MUL + 3 FFMA + 1 MUL].
__global__ __launch_bounds__(256) void fused_kernel(
    const float* __restrict__ x1, const int* __restrict__ idx1, const float* __restrict__ dm1,
    const float* __restrict__ x2, const int* __restrict__ idx2, const float* __restrict__ dm2,
    const float* __restrict__ w,  const float* __restrict__ b_out,
    float* __restrict__ op1, float* __restrict__ os1,
    float* __restrict__ op2, float* __restrict__ os2)
{
    const int br = blockIdx.y;
    const float* __restrict__ x   = br ? x2   : x1;
    const int*   __restrict__ idx = br ? idx2 : idx1;
    const float* __restrict__ dm  = br ? dm2  : dm1;
    float*       __restrict__ op  = br ? op2  : op1;
    float*       __restrict__ os  = br ? os2  : os1;

    const int warp = threadIdx.x >> 5;
    const int lane = threadIdx.x & 31;
    const int n    = blockIdx.x * 8 + warp;

    // Metadata for 2 k's per int4: (off_2p, dm_2p, off_2p+1, dm_2p+1).
    __shared__ int4 s_meta[8][16];

    // Lane l owns metadata for k == l.
    const int   a = idx[n * K_ANCH + lane];    // coalesced
    const float d = dm [n * K_ANCH + lane];    // coalesced
    {
        int2* dst = reinterpret_cast<int2*>(&s_meta[warp][0]) + lane;
        *dst = make_int2(a * (int)(D_FEAT * sizeof(float)), __float_as_int(d));
    }
    __syncwarp();

    // This lane's 4-wide slice of w.
    const float4 w4 = reinterpret_cast<const float4*>(w)[lane];

    const char* __restrict__ xb = reinterpret_cast<const char*>(x);
    const int lane_byte = lane * 16;

    float4 acc = make_float4(0.f, 0.f, 0.f, 0.f);

    float stk[6];
    int sp = 0;

    #pragma unroll
    for (int p = 0; p < 16; p++) {
        const int4 m = s_meta[warp][p];          // broadcast LDS.128
        const float d0 = __int_as_float(m.y);
        const float d1 = __int_as_float(m.w);
        const float4 v0 = __ldg(reinterpret_cast<const float4*>(xb + m.x + lane_byte));
        const float4 v1 = __ldg(reinterpret_cast<const float4*>(xb + m.z + lane_byte));

        // k = 2p : acc = fma(d0, v0, acc); o = d0 * dot(v0, w4)
        {
            acc.x = fmaf(d0, v0.x, acc.x);
            acc.y = fmaf(d0, v0.y, acc.y);
            acc.z = fmaf(d0, v0.z, acc.z);
            acc.w = fmaf(d0, v0.w, acc.w);
            float o = v0.x * w4.x;
            o = fmaf(v0.y, w4.y, o);
            o = fmaf(v0.z, w4.z, o);
            o = fmaf(v0.w, w4.w, o);
            stk[sp++] = d0 * o;
        }
        // k = 2p+1
        {
            acc.x = fmaf(d1, v1.x, acc.x);
            acc.y = fmaf(d1, v1.y, acc.y);
            acc.z = fmaf(d1, v1.z, acc.z);
            acc.w = fmaf(d1, v1.w, acc.w);
            float o = v1.x * w4.x;
            o = fmaf(v1.y, w4.y, o);
            o = fmaf(v1.z, w4.z, o);
            o = fmaf(v1.w, w4.w, o);
            stk[sp++] = d1 * o;
        }

        // Eager binary-counter folding, LSB-first.
        const int i1 = 2 * p + 2;   // items completed
        #pragma unroll
        for (int j = 0; j < 5; j++) {
            if ((i1 & ((2 << j) - 1)) == 0) {
                const int off = 1 << j;
                sp -= 2;
                stk[sp] = warp_fold(stk[sp], stk[sp + 1], off, lane);
                sp += 1;
            }
        }
    }

    // stk[0]: lane l holds op-value for k == l (pre-bias).
    const float opv = stk[0] + __ldg(&b_out[0]);

    const float inv = 1.0f / (float)K_ANCH;
    acc.x *= inv; acc.y *= inv; acc.z *= inv; acc.w *= inv;

    reinterpret_cast<float4*>(os)[n * (D_FEAT / 4) + lane] = acc;   // coalesced 512B
    op[n * K_ANCH + lane] = opv;                                    // coalesced 128B
}

extern "C" void kernel_launch(void* const* d_in, const int* in_sizes, int n_in,
                              void* d_out, int out_size) {
    const float* x1   = (const float*)d_in[0];
    const int*   idx1 = (const int*)  d_in[1];
    const float* dm1  = (const float*)d_in[2];
    const float* x2   = (const float*)d_in[3];
    const int*   idx2 = (const int*)  d_in[4];
    const float* dm2  = (const float*)d_in[5];
    const float* w    = (const float*)d_in[6];
    const float* b    = (const float*)d_in[7];

    float* out = (float*)d_out;
    float* op1 = out;                                       // [N, K]
    float* os1 = op1 + (size_t)N_ROWS * K_ANCH;             // [N, D]
    float* op2 = os1 + (size_t)N_ROWS * D_FEAT;             // [N, K]
    float* os2 = op2 + (size_t)N_ROWS * K_ANCH;             // [N, D]

    dim3 gg(N_ROWS / 8, 2);
    fused_kernel<<<gg, 256>>>(x1, idx1, dm1, x2, idx2, dm2, w, b,
                              op1, os1, op2, os2);
}